// round 14
// baseline (speedup 1.0000x reference)
#include <cuda_runtime.h>
#include <cuda_fp16.h>

#define VOCAB   50257
#define DIM     128
#define BATCH   32
#define M_SLOTS 512
#define S_TOK   6
#define T_TREE  128
#define L_TOK   64
#define SLOTS   (M_SLOTS + T_TREE)        // 640
#define TABN    ((size_t)VOCAB * DIM)     // floats per table
#define CN      (3 * TABN)

// gather decomposition (per table): tree slot = 2 halfwarps x 32 tokens;
// story = 2 slots per halfwarp
#define TREE_BLK_TAB  (BATCH * T_TREE / 8)     // 512 tree blocks
#define STORY_BLK_TAB (BATCH * M_SLOTS / 32)   // 512 story blocks
#define GBLK_TAB      (TREE_BLK_TAB + STORY_BLK_TAB)   // 1024
#define CB_TAB        ((int)((TABN / 8 + 255) / 256))  // 3142 convert blocks
#define NMIX          (GBLK_TAB + CB_TAB)              // 4166
#define HOP_T   512
#define HW_HOP  (HOP_T / 16)
#define SL_HW   (SLOTS / HW_HOP)          // 20

// fp16 tables 1..3 (38.6 MB) and fp16 slot memories (15.7 MB)
__device__ __align__(16) __half g_Ch[CN];
__device__ __align__(16) __half g_Mh[(size_t)3 * BATCH * SLOTS * DIM];

__device__ __forceinline__ float warp_max(float v) {
    #pragma unroll
    for (int o = 16; o; o >>= 1) v = fmaxf(v, __shfl_xor_sync(0xffffffffu, v, o));
    return v;
}
__device__ __forceinline__ float warp_sum(float v) {
    #pragma unroll
    for (int o = 16; o; o >>= 1) v += __shfl_xor_sync(0xffffffffu, v, o);
    return v;
}
__device__ __forceinline__ float hw_sum(float v) {
    #pragma unroll
    for (int o = 8; o; o >>= 1) v += __shfl_xor_sync(0xffffffffu, v, o);
    return v;
}
__device__ __forceinline__ void acc8(float4& lo, float4& hi, uint4 v) {
    float2 f;
    f = __half22float2(*reinterpret_cast<__half2*>(&v.x)); lo.x += f.x; lo.y += f.y;
    f = __half22float2(*reinterpret_cast<__half2*>(&v.y)); lo.z += f.x; lo.w += f.y;
    f = __half22float2(*reinterpret_cast<__half2*>(&v.z)); hi.x += f.x; hi.y += f.y;
    f = __half22float2(*reinterpret_cast<__half2*>(&v.w)); hi.z += f.x; hi.w += f.y;
}
__device__ __forceinline__ uint4 pack8(float4 lo, float4 hi) {
    union { __half2 h[4]; uint4 u; } cv;
    cv.h[0] = __floats2half2_rn(lo.x, lo.y);
    cv.h[1] = __floats2half2_rn(lo.z, lo.w);
    cv.h[2] = __floats2half2_rn(hi.x, hi.y);
    cv.h[3] = __floats2half2_rn(hi.z, hi.w);
    return cv.u;
}
__device__ __forceinline__ float dot8(uint4 v, const float* __restrict__ u) {
    float2 f; float s;
    f = __half22float2(*reinterpret_cast<__half2*>(&v.x)); s  = f.x * u[0] + f.y * u[1];
    f = __half22float2(*reinterpret_cast<__half2*>(&v.y)); s += f.x * u[2] + f.y * u[3];
    f = __half22float2(*reinterpret_cast<__half2*>(&v.z)); s += f.x * u[4] + f.y * u[5];
    f = __half22float2(*reinterpret_cast<__half2*>(&v.w)); s += f.x * u[6] + f.y * u[7];
    return s;
}
__device__ __forceinline__ void add4(float4& a, float4 b) {
    a.x += b.x; a.y += b.y; a.z += b.z; a.w += b.w;
}

// ---------------------------------------------------------------------------
// convert one block of table (tab+1) -> g_Ch[tab]
// ---------------------------------------------------------------------------
__device__ __forceinline__ void convert_body(const float* __restrict__ C,
                                             int tab, int cb)
{
    const size_t i = ((size_t)cb * 256 + threadIdx.x) * 8;
    if (i >= TABN) return;
    const float4* src =
        reinterpret_cast<const float4*>(C + (size_t)(tab + 1) * TABN + i);
    float4 a = __ldcs(src);
    float4 b = __ldcs(src + 1);
    union { __half2 h[4]; uint4 u; } cv;
    cv.h[0] = __floats2half2_rn(a.x, a.y);
    cv.h[1] = __floats2half2_rn(a.z, a.w);
    cv.h[2] = __floats2half2_rn(b.x, b.y);
    cv.h[3] = __floats2half2_rn(b.z, b.w);
    *reinterpret_cast<uint4*>(g_Ch + (size_t)tab * TABN + i) = cv.u;
}

// ---------------------------------------------------------------------------
// deep-MLP gather, one block r of table tab
// ---------------------------------------------------------------------------
__device__ __forceinline__ void gather_body(const int* __restrict__ story,
                                            const int* __restrict__ kb,
                                            int tab, int r)
{
    const int hw = threadIdx.x >> 4;
    const int hl = threadIdx.x & 15;
    const __half* __restrict__ Ct = g_Ch + (size_t)tab * TABN;

    if (r < TREE_BLK_TAB) {
        // tree: 8 trees per block, 2 halfwarps per tree, 32 tokens each
        __shared__ float4 s_lo[16][16];
        __shared__ float4 s_hi[16][16];

        const int unit = r * 8 + (hw >> 1);
        const int b    = unit / T_TREE;
        const int tr   = unit % T_TREE;
        const int sub  = hw & 1;

        const int* toks = kb + ((size_t)b * T_TREE + tr) * L_TOK + sub * 32;
        float4 lo = make_float4(0.f, 0.f, 0.f, 0.f), hi = lo;
        float4 lo1 = lo, hi1 = hi;
        #pragma unroll
        for (int j = 0; j < 32; j += 2) {
            int t0 = toks[j], t1 = toks[j + 1];
            uint4 v0 = reinterpret_cast<const uint4*>(Ct + (size_t)t0 * DIM)[hl];
            uint4 v1 = reinterpret_cast<const uint4*>(Ct + (size_t)t1 * DIM)[hl];
            acc8(lo, hi, v0);
            acc8(lo1, hi1, v1);
        }
        add4(lo, lo1); add4(hi, hi1);

        s_lo[hw][hl] = lo;
        s_hi[hw][hl] = hi;
        __syncthreads();

        if (sub == 0) {
            add4(lo, s_lo[hw + 1][hl]);
            add4(hi, s_hi[hw + 1][hl]);
            const int slot = M_SLOTS + tr;
            reinterpret_cast<uint4*>(
                g_Mh + ((size_t)(tab * BATCH + b) * SLOTS + slot) * DIM)[hl] =
                pack8(lo, hi);
        }
    } else {
        // story: halfwarp per 2 slots (12 independent loads in flight)
        const int pair = (r - TREE_BLK_TAB) * 16 + hw;
        const int b    = pair / (M_SLOTS / 2);
        const int s0   = (pair % (M_SLOTS / 2)) * 2;

        const int* t0p = story + ((size_t)b * M_SLOTS + s0) * S_TOK;
        int tka[S_TOK], tkb[S_TOK];
        #pragma unroll
        for (int j = 0; j < S_TOK; ++j) { tka[j] = t0p[j]; tkb[j] = t0p[S_TOK + j]; }

        float4 loA = make_float4(0.f, 0.f, 0.f, 0.f), hiA = loA;
        float4 loB = loA, hiB = loA;
        #pragma unroll
        for (int j = 0; j < S_TOK; ++j) {
            uint4 va = reinterpret_cast<const uint4*>(Ct + (size_t)tka[j] * DIM)[hl];
            uint4 vb = reinterpret_cast<const uint4*>(Ct + (size_t)tkb[j] * DIM)[hl];
            acc8(loA, hiA, va);
            acc8(loB, hiB, vb);
        }
        uint4* dst = reinterpret_cast<uint4*>(
            g_Mh + ((size_t)(tab * BATCH + b) * SLOTS + s0) * DIM);
        dst[hl]      = pack8(loA, hiA);
        dst[16 + hl] = pack8(loB, hiB);
    }
}

// ---------------------------------------------------------------------------
// K1: convert table 1 only.
// ---------------------------------------------------------------------------
__global__ void __launch_bounds__(256) conv_kernel(const float* __restrict__ C,
                                                   int tab)
{
    convert_body(C, tab, blockIdx.x);
}

// Kmix: gather table gtab interleaved 1:4 with convert of table gtab+1.
__global__ void __launch_bounds__(256) mix_kernel(
    const float* __restrict__ C, const int* __restrict__ story,
    const int* __restrict__ kb, int gtab)
{
    const int i = blockIdx.x;
    if ((i & 3) == 0 && i < 4 * GBLK_TAB) {
        gather_body(story, kb, gtab, i >> 2);
    } else {
        const int g_before = (i < 4 * GBLK_TAB) ? ((i + 3) >> 2) : GBLK_TAB;
        convert_body(C, gtab + 1, i - g_before);
    }
}

// K4: gather table 3 only.
__global__ void __launch_bounds__(256) gather_kernel(
    const int* __restrict__ story, const int* __restrict__ kb, int tab)
{
    gather_body(story, kb, tab, blockIdx.x);
}

// ---------------------------------------------------------------------------
// K5: whole 3-hop chain, one block per batch element.
// ---------------------------------------------------------------------------
__global__ void __launch_bounds__(HOP_T) hops_kernel(float* __restrict__ out)
{
    __shared__ float s_score[SLOTS];
    __shared__ float s_part[HW_HOP][DIM];
    __shared__ float s_u[DIM];
    __shared__ float s_red[16];

    const int b    = blockIdx.x;
    const int tid  = threadIdx.x;
    const int w    = tid >> 5;
    const int lane = tid & 31;
    const int hw   = tid >> 4;
    const int hl   = tid & 15;

    const __half* __restrict__ M1 = g_Mh + (size_t)(0 * BATCH + b) * SLOTS * DIM;
    const __half* __restrict__ M2 = g_Mh + (size_t)(1 * BATCH + b) * SLOTS * DIM;
    const __half* __restrict__ M3 = g_Mh + (size_t)(2 * BATCH + b) * SLOTS * DIM;

    // u1 = mean over slots of M1
    {
        float4 lo = make_float4(0.f, 0.f, 0.f, 0.f), hi = lo;
        #pragma unroll 5
        for (int k = 0; k < SL_HW; ++k) {
            uint4 v = reinterpret_cast<const uint4*>(
                M1 + (size_t)(hw * SL_HW + k) * DIM)[hl];
            acc8(lo, hi, v);
        }
        float* p = &s_part[hw][hl * 8];
        p[0] = lo.x; p[1] = lo.y; p[2] = lo.z; p[3] = lo.w;
        p[4] = hi.x; p[5] = hi.y; p[6] = hi.z; p[7] = hi.w;
    }
    __syncthreads();
    if (tid < DIM) {
        float s = 0.f;
        #pragma unroll
        for (int i = 0; i < HW_HOP; ++i) s += s_part[i][tid];
        s_u[tid] = s * (1.0f / SLOTS);
    }
    __syncthreads();

    #pragma unroll
    for (int hop = 0; hop < 2; ++hop) {
        const __half* Mk = (hop == 0) ? M1 : M2;
        const __half* Mv = (hop == 0) ? M2 : M3;

        float ur[8];
        #pragma unroll
        for (int j = 0; j < 8; ++j) ur[j] = s_u[hl * 8 + j];

        #pragma unroll 5
        for (int k = 0; k < SL_HW; ++k) {
            const int slot = hw * SL_HW + k;
            uint4 v = reinterpret_cast<const uint4*>(Mk + (size_t)slot * DIM)[hl];
            float p = hw_sum(dot8(v, ur));
            if (hl == 0) s_score[slot] = p;
        }
        __syncthreads();

        float mx = -1e30f;
        for (int i = tid; i < SLOTS; i += HOP_T) mx = fmaxf(mx, s_score[i]);
        mx = warp_max(mx);
        if (lane == 0) s_red[w] = mx;
        __syncthreads();
        mx = s_red[0];
        #pragma unroll
        for (int i = 1; i < 16; ++i) mx = fmaxf(mx, s_red[i]);

        float ss = 0.f;
        for (int i = tid; i < SLOTS; i += HOP_T) {
            float e = __expf(s_score[i] - mx);
            s_score[i] = e;
            ss += e;
        }
        ss = warp_sum(ss);
        __syncthreads();
        if (lane == 0) s_red[w] = ss;
        __syncthreads();
        ss = 0.f;
        #pragma unroll
        for (int i = 0; i < 16; ++i) ss += s_red[i];
        const float inv = 1.0f / ss;

        {
            float4 lo = make_float4(0.f, 0.f, 0.f, 0.f), hi = lo;
            #pragma unroll 5
            for (int k = 0; k < SL_HW; ++k) {
                const int slot = hw * SL_HW + k;
                const float p = s_score[slot];
                uint4 v = reinterpret_cast<const uint4*>(Mv + (size_t)slot * DIM)[hl];
                float2 f;
                f = __half22float2(*reinterpret_cast<__half2*>(&v.x)); lo.x += p * f.x; lo.y += p * f.y;
                f = __half22float2(*reinterpret_cast<__half2*>(&v.y)); lo.z += p * f.x; lo.w += p * f.y;
                f = __half22float2(*reinterpret_cast<__half2*>(&v.z)); hi.x += p * f.x; hi.y += p * f.y;
                f = __half22float2(*reinterpret_cast<__half2*>(&v.w)); hi.z += p * f.x; hi.w += p * f.y;
            }
            float* p = &s_part[hw][hl * 8];
            p[0] = lo.x; p[1] = lo.y; p[2] = lo.z; p[3] = lo.w;
            p[4] = hi.x; p[5] = hi.y; p[6] = hi.z; p[7] = hi.w;
        }
        __syncthreads();

        if (tid < DIM) {
            float o = 0.f;
            #pragma unroll
            for (int i = 0; i < HW_HOP; ++i) o += s_part[i][tid];
            const float un = s_u[tid] + o * inv;
            if (hop == 0) s_u[tid] = un;
            else          out[b * DIM + tid] = un;
        }
        __syncthreads();
    }
}

// ---------------------------------------------------------------------------
extern "C" void kernel_launch(void* const* d_in, const int* in_sizes, int n_in,
                              void* d_out, int out_size)
{
    const float* C     = (const float*)d_in[0];  // [4, 50257, 128]
    const int*   story = (const int*)  d_in[1];  // [32, 512, 6]
    const int*   kb    = (const int*)  d_in[2];  // [32, 128, 64]
    float*       out   = (float*)d_out;          // [32, 128]

    conv_kernel<<<CB_TAB, 256>>>(C, 0);              // conv T1
    mix_kernel<<<NMIX, 256>>>(C, story, kb, 0);      // gather T1 ⋈ conv T2
    mix_kernel<<<NMIX, 256>>>(C, story, kb, 1);      // gather T2 ⋈ conv T3
    gather_kernel<<<GBLK_TAB, 256>>>(story, kb, 2);  // gather T3
    hops_kernel<<<BATCH, HOP_T>>>(out);              // 3-hop chain
}

// round 15
// speedup vs baseline: 1.1567x; 1.1567x over previous
#include <cuda_runtime.h>
#include <cuda_fp16.h>

#define VOCAB   50257
#define DIM     128
#define BATCH   32
#define M_SLOTS 512
#define S_TOK   6
#define T_TREE  128
#define L_TOK   64
#define SLOTS   (M_SLOTS + T_TREE)        // 640
#define TABN    ((size_t)VOCAB * DIM)     // floats per table
#define CN      (3 * TABN)

// gather decomposition: tree slot = 2 halfwarps x 32 tokens; story = 2 slots/halfwarp
#define TREE_BLK_TAB  (BATCH * T_TREE / 8)     // 512 blocks per table
#define STORY_BLK_TAB (BATCH * M_SLOTS / 32)   // 512 blocks per table
#define GBLK_TAB      (TREE_BLK_TAB + STORY_BLK_TAB)   // 1024
#define HOP_T   512
#define HW_HOP  (HOP_T / 16)              // 32 halfwarps per hop block
#define SL_HW   (SLOTS / HW_HOP)          // 20 slots per halfwarp

// fp16 tables 1..3 (38.6 MB) and fp16 slot memories (15.7 MB)
__device__ __align__(16) __half g_Ch[CN];
__device__ __align__(16) __half g_Mh[(size_t)3 * BATCH * SLOTS * DIM];

__device__ __forceinline__ float warp_max(float v) {
    #pragma unroll
    for (int o = 16; o; o >>= 1) v = fmaxf(v, __shfl_xor_sync(0xffffffffu, v, o));
    return v;
}
__device__ __forceinline__ float warp_sum(float v) {
    #pragma unroll
    for (int o = 16; o; o >>= 1) v += __shfl_xor_sync(0xffffffffu, v, o);
    return v;
}
__device__ __forceinline__ float hw_sum(float v) {
    #pragma unroll
    for (int o = 8; o; o >>= 1) v += __shfl_xor_sync(0xffffffffu, v, o);
    return v;
}
__device__ __forceinline__ void acc8(float4& lo, float4& hi, uint4 v) {
    float2 f;
    f = __half22float2(*reinterpret_cast<__half2*>(&v.x)); lo.x += f.x; lo.y += f.y;
    f = __half22float2(*reinterpret_cast<__half2*>(&v.y)); lo.z += f.x; lo.w += f.y;
    f = __half22float2(*reinterpret_cast<__half2*>(&v.z)); hi.x += f.x; hi.y += f.y;
    f = __half22float2(*reinterpret_cast<__half2*>(&v.w)); hi.z += f.x; hi.w += f.y;
}
// fp16 pairwise add of two 8-element rows (4x HADD2)
__device__ __forceinline__ uint4 hadd_u4(uint4 a, uint4 b) {
    uint4 r;
    *reinterpret_cast<__half2*>(&r.x) =
        __hadd2(*reinterpret_cast<__half2*>(&a.x), *reinterpret_cast<__half2*>(&b.x));
    *reinterpret_cast<__half2*>(&r.y) =
        __hadd2(*reinterpret_cast<__half2*>(&a.y), *reinterpret_cast<__half2*>(&b.y));
    *reinterpret_cast<__half2*>(&r.z) =
        __hadd2(*reinterpret_cast<__half2*>(&a.z), *reinterpret_cast<__half2*>(&b.z));
    *reinterpret_cast<__half2*>(&r.w) =
        __hadd2(*reinterpret_cast<__half2*>(&a.w), *reinterpret_cast<__half2*>(&b.w));
    return r;
}
__device__ __forceinline__ uint4 pack8(float4 lo, float4 hi) {
    union { __half2 h[4]; uint4 u; } cv;
    cv.h[0] = __floats2half2_rn(lo.x, lo.y);
    cv.h[1] = __floats2half2_rn(lo.z, lo.w);
    cv.h[2] = __floats2half2_rn(hi.x, hi.y);
    cv.h[3] = __floats2half2_rn(hi.z, hi.w);
    return cv.u;
}
__device__ __forceinline__ float dot8(uint4 v, const float* __restrict__ u) {
    float2 f; float s;
    f = __half22float2(*reinterpret_cast<__half2*>(&v.x)); s  = f.x * u[0] + f.y * u[1];
    f = __half22float2(*reinterpret_cast<__half2*>(&v.y)); s += f.x * u[2] + f.y * u[3];
    f = __half22float2(*reinterpret_cast<__half2*>(&v.z)); s += f.x * u[4] + f.y * u[5];
    f = __half22float2(*reinterpret_cast<__half2*>(&v.w)); s += f.x * u[6] + f.y * u[7];
    return s;
}
__device__ __forceinline__ void add4(float4& a, float4 b) {
    a.x += b.x; a.y += b.y; a.z += b.z; a.w += b.w;
}

// ---------------------------------------------------------------------------
// K1: convert C tables 1..3 to fp16; 16 floats per thread for ILP.
// ---------------------------------------------------------------------------
__global__ void __launch_bounds__(256) convert_kernel(const float* __restrict__ C)
{
    const size_t i = ((size_t)blockIdx.x * 256 + threadIdx.x) * 16;
    if (i >= CN) return;
    const float4* src = reinterpret_cast<const float4*>(C + TABN + i);
    float4 a = __ldcs(src);
    float4 b = __ldcs(src + 1);
    float4 c = __ldcs(src + 2);
    float4 d = __ldcs(src + 3);
    union { __half2 h[4]; uint4 u; } cv0, cv1;
    cv0.h[0] = __floats2half2_rn(a.x, a.y);
    cv0.h[1] = __floats2half2_rn(a.z, a.w);
    cv0.h[2] = __floats2half2_rn(b.x, b.y);
    cv0.h[3] = __floats2half2_rn(b.z, b.w);
    cv1.h[0] = __floats2half2_rn(c.x, c.y);
    cv1.h[1] = __floats2half2_rn(c.z, c.w);
    cv1.h[2] = __floats2half2_rn(d.x, d.y);
    cv1.h[3] = __floats2half2_rn(d.z, d.w);
    uint4* dst = reinterpret_cast<uint4*>(g_Ch + i);
    dst[0] = cv0.u;
    dst[1] = cv1.u;
}

// ---------------------------------------------------------------------------
// K2: gather (R13 shape) with fp16 pairwise adds to cut issue count.
//   tree  block: 8 trees x 2 halfwarps x 32 tokens, smem pair-combine
//   story block: 16 halfwarps x 2 slots x 6 tokens
// ---------------------------------------------------------------------------
__global__ void __launch_bounds__(256) gather_kernel(
    const int* __restrict__ story, const int* __restrict__ kb)
{
    const int hw  = threadIdx.x >> 4;
    const int hl  = threadIdx.x & 15;
    const int tab = blockIdx.x / GBLK_TAB;
    const int r   = blockIdx.x % GBLK_TAB;

    const __half* __restrict__ Ct = g_Ch + (size_t)tab * TABN;

    if (r < TREE_BLK_TAB) {
        // ---- tree: 8 trees per block, 2 halfwarps per tree, 32 tokens each
        __shared__ float4 s_lo[16][16];
        __shared__ float4 s_hi[16][16];

        const int unit = r * 8 + (hw >> 1);
        const int b    = unit / T_TREE;
        const int tr   = unit % T_TREE;
        const int sub  = hw & 1;

        const int* toks = kb + ((size_t)b * T_TREE + tr) * L_TOK + sub * 32;
        float4 lo = make_float4(0.f, 0.f, 0.f, 0.f), hi = lo;
        float4 lo1 = lo, hi1 = hi;
        // 32 tokens = 8 groups of 4; each group: 2 fp16 pair-adds -> 2 fp32 acc
        #pragma unroll
        for (int j = 0; j < 32; j += 4) {
            int t0 = toks[j],     t1 = toks[j + 1];
            int t2 = toks[j + 2], t3 = toks[j + 3];
            uint4 v0 = reinterpret_cast<const uint4*>(Ct + (size_t)t0 * DIM)[hl];
            uint4 v1 = reinterpret_cast<const uint4*>(Ct + (size_t)t1 * DIM)[hl];
            uint4 v2 = reinterpret_cast<const uint4*>(Ct + (size_t)t2 * DIM)[hl];
            uint4 v3 = reinterpret_cast<const uint4*>(Ct + (size_t)t3 * DIM)[hl];
            acc8(lo,  hi,  hadd_u4(v0, v1));
            acc8(lo1, hi1, hadd_u4(v2, v3));
        }
        add4(lo, lo1); add4(hi, hi1);

        s_lo[hw][hl] = lo;
        s_hi[hw][hl] = hi;
        __syncthreads();

        if (sub == 0) {
            add4(lo, s_lo[hw + 1][hl]);
            add4(hi, s_hi[hw + 1][hl]);
            const int slot = M_SLOTS + tr;
            reinterpret_cast<uint4*>(
                g_Mh + ((size_t)(tab * BATCH + b) * SLOTS + slot) * DIM)[hl] =
                pack8(lo, hi);
        }
    } else {
        // ---- story: halfwarp per 2 slots; 6 tokens = 3 fp16 pairs each
        const int pair = (r - TREE_BLK_TAB) * 16 + hw;
        const int b    = pair / (M_SLOTS / 2);
        const int s0   = (pair % (M_SLOTS / 2)) * 2;

        const int* t0p = story + ((size_t)b * M_SLOTS + s0) * S_TOK;
        int tka[S_TOK], tkb[S_TOK];
        #pragma unroll
        for (int j = 0; j < S_TOK; ++j) { tka[j] = t0p[j]; tkb[j] = t0p[S_TOK + j]; }

        float4 loA = make_float4(0.f, 0.f, 0.f, 0.f), hiA = loA;
        float4 loB = loA, hiB = loA;
        #pragma unroll
        for (int j = 0; j < S_TOK; j += 2) {
            uint4 va0 = reinterpret_cast<const uint4*>(Ct + (size_t)tka[j]     * DIM)[hl];
            uint4 va1 = reinterpret_cast<const uint4*>(Ct + (size_t)tka[j + 1] * DIM)[hl];
            uint4 vb0 = reinterpret_cast<const uint4*>(Ct + (size_t)tkb[j]     * DIM)[hl];
            uint4 vb1 = reinterpret_cast<const uint4*>(Ct + (size_t)tkb[j + 1] * DIM)[hl];
            acc8(loA, hiA, hadd_u4(va0, va1));
            acc8(loB, hiB, hadd_u4(vb0, vb1));
        }
        uint4* dst = reinterpret_cast<uint4*>(
            g_Mh + ((size_t)(tab * BATCH + b) * SLOTS + s0) * DIM);
        dst[hl]      = pack8(loA, hiA);
        dst[16 + hl] = pack8(loB, hiB);
    }
}

// ---------------------------------------------------------------------------
// K3: whole 3-hop chain, one block per batch element.
// ---------------------------------------------------------------------------
__global__ void __launch_bounds__(HOP_T) hops_kernel(float* __restrict__ out)
{
    __shared__ float s_score[SLOTS];
    __shared__ float s_part[HW_HOP][DIM];
    __shared__ float s_u[DIM];
    __shared__ float s_red[16];

    const int b    = blockIdx.x;
    const int tid  = threadIdx.x;
    const int w    = tid >> 5;
    const int lane = tid & 31;
    const int hw   = tid >> 4;
    const int hl   = tid & 15;

    const __half* __restrict__ M1 = g_Mh + (size_t)(0 * BATCH + b) * SLOTS * DIM;
    const __half* __restrict__ M2 = g_Mh + (size_t)(1 * BATCH + b) * SLOTS * DIM;
    const __half* __restrict__ M3 = g_Mh + (size_t)(2 * BATCH + b) * SLOTS * DIM;

    // u1 = mean over slots of M1
    {
        float4 lo = make_float4(0.f, 0.f, 0.f, 0.f), hi = lo;
        #pragma unroll 5
        for (int k = 0; k < SL_HW; ++k) {
            uint4 v = reinterpret_cast<const uint4*>(
                M1 + (size_t)(hw * SL_HW + k) * DIM)[hl];
            acc8(lo, hi, v);
        }
        float* p = &s_part[hw][hl * 8];
        p[0] = lo.x; p[1] = lo.y; p[2] = lo.z; p[3] = lo.w;
        p[4] = hi.x; p[5] = hi.y; p[6] = hi.z; p[7] = hi.w;
    }
    __syncthreads();
    if (tid < DIM) {
        float s = 0.f;
        #pragma unroll
        for (int i = 0; i < HW_HOP; ++i) s += s_part[i][tid];
        s_u[tid] = s * (1.0f / SLOTS);
    }
    __syncthreads();

    #pragma unroll
    for (int hop = 0; hop < 2; ++hop) {
        const __half* Mk = (hop == 0) ? M1 : M2;
        const __half* Mv = (hop == 0) ? M2 : M3;

        float ur[8];
        #pragma unroll
        for (int j = 0; j < 8; ++j) ur[j] = s_u[hl * 8 + j];

        #pragma unroll 5
        for (int k = 0; k < SL_HW; ++k) {
            const int slot = hw * SL_HW + k;
            uint4 v = reinterpret_cast<const uint4*>(Mk + (size_t)slot * DIM)[hl];
            float p = hw_sum(dot8(v, ur));
            if (hl == 0) s_score[slot] = p;
        }
        __syncthreads();

        float mx = -1e30f;
        for (int i = tid; i < SLOTS; i += HOP_T) mx = fmaxf(mx, s_score[i]);
        mx = warp_max(mx);
        if (lane == 0) s_red[w] = mx;
        __syncthreads();
        mx = s_red[0];
        #pragma unroll
        for (int i = 1; i < 16; ++i) mx = fmaxf(mx, s_red[i]);

        float ss = 0.f;
        for (int i = tid; i < SLOTS; i += HOP_T) {
            float e = __expf(s_score[i] - mx);
            s_score[i] = e;
            ss += e;
        }
        ss = warp_sum(ss);
        __syncthreads();
        if (lane == 0) s_red[w] = ss;
        __syncthreads();
        ss = 0.f;
        #pragma unroll
        for (int i = 0; i < 16; ++i) ss += s_red[i];
        const float inv = 1.0f / ss;

        {
            float4 lo = make_float4(0.f, 0.f, 0.f, 0.f), hi = lo;
            #pragma unroll 5
            for (int k = 0; k < SL_HW; ++k) {
                const int slot = hw * SL_HW + k;
                const float p = s_score[slot];
                uint4 v = reinterpret_cast<const uint4*>(Mv + (size_t)slot * DIM)[hl];
                float2 f;
                f = __half22float2(*reinterpret_cast<__half2*>(&v.x)); lo.x += p * f.x; lo.y += p * f.y;
                f = __half22float2(*reinterpret_cast<__half2*>(&v.y)); lo.z += p * f.x; lo.w += p * f.y;
                f = __half22float2(*reinterpret_cast<__half2*>(&v.z)); hi.x += p * f.x; hi.y += p * f.y;
                f = __half22float2(*reinterpret_cast<__half2*>(&v.w)); hi.z += p * f.x; hi.w += p * f.y;
            }
            float* p = &s_part[hw][hl * 8];
            p[0] = lo.x; p[1] = lo.y; p[2] = lo.z; p[3] = lo.w;
            p[4] = hi.x; p[5] = hi.y; p[6] = hi.z; p[7] = hi.w;
        }
        __syncthreads();

        if (tid < DIM) {
            float o = 0.f;
            #pragma unroll
            for (int i = 0; i < HW_HOP; ++i) o += s_part[i][tid];
            const float un = s_u[tid] + o * inv;
            if (hop == 0) s_u[tid] = un;
            else          out[b * DIM + tid] = un;
        }
        __syncthreads();
    }
}

// ---------------------------------------------------------------------------
extern "C" void kernel_launch(void* const* d_in, const int* in_sizes, int n_in,
                              void* d_out, int out_size)
{
    const float* C     = (const float*)d_in[0];  // [4, 50257, 128]
    const int*   story = (const int*)  d_in[1];  // [32, 512, 6]
    const int*   kb    = (const int*)  d_in[2];  // [32, 128, 64]
    float*       out   = (float*)d_out;          // [32, 128]

    const int cb = (int)((CN / 16 + 255) / 256);             // 4712
    convert_kernel<<<cb, 256>>>(C);                          // fp32 -> fp16
    gather_kernel<<<3 * GBLK_TAB, 256>>>(story, kb);         // pairwise-fp16 gather
    hops_kernel<<<BATCH, HOP_T>>>(out);                      // 3-hop chain
}

// round 16
// speedup vs baseline: 1.2308x; 1.0640x over previous
#include <cuda_runtime.h>
#include <cuda_fp16.h>

#define VOCAB   50257
#define DIM     128
#define BATCH   32
#define M_SLOTS 512
#define S_TOK   6
#define T_TREE  128
#define L_TOK   64
#define SLOTS   (M_SLOTS + T_TREE)        // 640
#define TABN    ((size_t)VOCAB * DIM)     // floats per table
#define CN      (3 * TABN)

// gather decomposition: tree slot = 1 halfwarp x 64 tokens (no smem);
// story = 2 slots per halfwarp
#define TREE_BLK_TAB  (BATCH * T_TREE / 16)    // 256 blocks per table
#define STORY_BLK_TAB (BATCH * M_SLOTS / 32)   // 512 blocks per table
#define GBLK_TAB      (TREE_BLK_TAB + STORY_BLK_TAB)   // 768
#define HOP_T   512
#define HW_HOP  (HOP_T / 16)              // 32 halfwarps per hop block
#define SL_HW   (SLOTS / HW_HOP)          // 20 slots per halfwarp

// fp16 tables 1..3 (38.6 MB) and fp16 slot memories (15.7 MB)
__device__ __align__(16) __half g_Ch[CN];
__device__ __align__(16) __half g_Mh[(size_t)3 * BATCH * SLOTS * DIM];

__device__ __forceinline__ float warp_max(float v) {
    #pragma unroll
    for (int o = 16; o; o >>= 1) v = fmaxf(v, __shfl_xor_sync(0xffffffffu, v, o));
    return v;
}
__device__ __forceinline__ float warp_sum(float v) {
    #pragma unroll
    for (int o = 16; o; o >>= 1) v += __shfl_xor_sync(0xffffffffu, v, o);
    return v;
}
__device__ __forceinline__ float hw_sum(float v) {
    #pragma unroll
    for (int o = 8; o; o >>= 1) v += __shfl_xor_sync(0xffffffffu, v, o);
    return v;
}
__device__ __forceinline__ void acc8(float4& lo, float4& hi, uint4 v) {
    float2 f;
    f = __half22float2(*reinterpret_cast<__half2*>(&v.x)); lo.x += f.x; lo.y += f.y;
    f = __half22float2(*reinterpret_cast<__half2*>(&v.y)); lo.z += f.x; lo.w += f.y;
    f = __half22float2(*reinterpret_cast<__half2*>(&v.z)); hi.x += f.x; hi.y += f.y;
    f = __half22float2(*reinterpret_cast<__half2*>(&v.w)); hi.z += f.x; hi.w += f.y;
}
// fp16 pairwise add of two 8-element rows (4x HADD2)
__device__ __forceinline__ uint4 hadd_u4(uint4 a, uint4 b) {
    uint4 r;
    *reinterpret_cast<__half2*>(&r.x) =
        __hadd2(*reinterpret_cast<__half2*>(&a.x), *reinterpret_cast<__half2*>(&b.x));
    *reinterpret_cast<__half2*>(&r.y) =
        __hadd2(*reinterpret_cast<__half2*>(&a.y), *reinterpret_cast<__half2*>(&b.y));
    *reinterpret_cast<__half2*>(&r.z) =
        __hadd2(*reinterpret_cast<__half2*>(&a.z), *reinterpret_cast<__half2*>(&b.z));
    *reinterpret_cast<__half2*>(&r.w) =
        __hadd2(*reinterpret_cast<__half2*>(&a.w), *reinterpret_cast<__half2*>(&b.w));
    return r;
}
__device__ __forceinline__ uint4 pack8(float4 lo, float4 hi) {
    union { __half2 h[4]; uint4 u; } cv;
    cv.h[0] = __floats2half2_rn(lo.x, lo.y);
    cv.h[1] = __floats2half2_rn(lo.z, lo.w);
    cv.h[2] = __floats2half2_rn(hi.x, hi.y);
    cv.h[3] = __floats2half2_rn(hi.z, hi.w);
    return cv.u;
}
__device__ __forceinline__ float dot8(uint4 v, const float* __restrict__ u) {
    float2 f; float s;
    f = __half22float2(*reinterpret_cast<__half2*>(&v.x)); s  = f.x * u[0] + f.y * u[1];
    f = __half22float2(*reinterpret_cast<__half2*>(&v.y)); s += f.x * u[2] + f.y * u[3];
    f = __half22float2(*reinterpret_cast<__half2*>(&v.z)); s += f.x * u[4] + f.y * u[5];
    f = __half22float2(*reinterpret_cast<__half2*>(&v.w)); s += f.x * u[6] + f.y * u[7];
    return s;
}
__device__ __forceinline__ void add4(float4& a, float4 b) {
    a.x += b.x; a.y += b.y; a.z += b.z; a.w += b.w;
}

// ---------------------------------------------------------------------------
// K1: convert C tables 1..3 to fp16 (R13 version: 8 floats/thread).
// ---------------------------------------------------------------------------
__global__ void __launch_bounds__(256) convert_kernel(const float* __restrict__ C)
{
    const size_t i = ((size_t)blockIdx.x * 256 + threadIdx.x) * 8;
    if (i >= CN) return;
    const float4* src = reinterpret_cast<const float4*>(C + TABN + i);
    float4 a = __ldcs(src);
    float4 b = __ldcs(src + 1);
    union { __half2 h[4]; uint4 u; } cv;
    cv.h[0] = __floats2half2_rn(a.x, a.y);
    cv.h[1] = __floats2half2_rn(a.z, a.w);
    cv.h[2] = __floats2half2_rn(b.x, b.y);
    cv.h[3] = __floats2half2_rn(b.z, b.w);
    *reinterpret_cast<uint4*>(g_Ch + i) = cv.u;
}

// ---------------------------------------------------------------------------
// K2: gather. Tree: 1 halfwarp per tree, 64 tokens, no smem/sync.
//     Story: halfwarp per 2 slots. occ-5 launch bounds for high residency.
// ---------------------------------------------------------------------------
__global__ void __launch_bounds__(256, 5) gather_kernel(
    const int* __restrict__ story, const int* __restrict__ kb)
{
    const int hw  = threadIdx.x >> 4;
    const int hl  = threadIdx.x & 15;
    const int tab = blockIdx.x / GBLK_TAB;
    const int r   = blockIdx.x % GBLK_TAB;

    const __half* __restrict__ Ct = g_Ch + (size_t)tab * TABN;

    if (r < TREE_BLK_TAB) {
        // ---- tree: 16 trees per block, 1 halfwarp per tree, 64 tokens ----
        const int unit = r * 16 + hw;                // global tree idx 0..4095
        const int b    = unit / T_TREE;
        const int tr   = unit % T_TREE;

        const int4* __restrict__ toks4 =
            reinterpret_cast<const int4*>(kb + ((size_t)b * T_TREE + tr) * L_TOK);

        float4 loA = make_float4(0.f, 0.f, 0.f, 0.f), hiA = loA;
        float4 loB = loA, hiB = loA;

        #pragma unroll
        for (int g = 0; g < 8; ++g) {                // 8 groups of 8 tokens
            int4 i0 = toks4[2 * g];
            int4 i1 = toks4[2 * g + 1];
            uint4 v0 = reinterpret_cast<const uint4*>(Ct + (size_t)i0.x * DIM)[hl];
            uint4 v1 = reinterpret_cast<const uint4*>(Ct + (size_t)i0.y * DIM)[hl];
            uint4 v2 = reinterpret_cast<const uint4*>(Ct + (size_t)i0.z * DIM)[hl];
            uint4 v3 = reinterpret_cast<const uint4*>(Ct + (size_t)i0.w * DIM)[hl];
            uint4 v4 = reinterpret_cast<const uint4*>(Ct + (size_t)i1.x * DIM)[hl];
            uint4 v5 = reinterpret_cast<const uint4*>(Ct + (size_t)i1.y * DIM)[hl];
            uint4 v6 = reinterpret_cast<const uint4*>(Ct + (size_t)i1.z * DIM)[hl];
            uint4 v7 = reinterpret_cast<const uint4*>(Ct + (size_t)i1.w * DIM)[hl];
            acc8(loA, hiA, hadd_u4(v0, v1));
            acc8(loB, hiB, hadd_u4(v2, v3));
            acc8(loA, hiA, hadd_u4(v4, v5));
            acc8(loB, hiB, hadd_u4(v6, v7));
        }
        add4(loA, loB); add4(hiA, hiB);

        const int slot = M_SLOTS + tr;
        reinterpret_cast<uint4*>(
            g_Mh + ((size_t)(tab * BATCH + b) * SLOTS + slot) * DIM)[hl] =
            pack8(loA, hiA);
    } else {
        // ---- story: halfwarp per 2 slots, 12 independent loads in flight ----
        const int pair = (r - TREE_BLK_TAB) * 16 + hw;
        const int b    = pair / (M_SLOTS / 2);
        const int s0   = (pair % (M_SLOTS / 2)) * 2;

        const int* t0p = story + ((size_t)b * M_SLOTS + s0) * S_TOK;
        int tka[S_TOK], tkb[S_TOK];
        #pragma unroll
        for (int j = 0; j < S_TOK; ++j) { tka[j] = t0p[j]; tkb[j] = t0p[S_TOK + j]; }

        float4 loA = make_float4(0.f, 0.f, 0.f, 0.f), hiA = loA;
        float4 loB = loA, hiB = loA;
        #pragma unroll
        for (int j = 0; j < S_TOK; ++j) {
            uint4 va = reinterpret_cast<const uint4*>(Ct + (size_t)tka[j] * DIM)[hl];
            uint4 vb = reinterpret_cast<const uint4*>(Ct + (size_t)tkb[j] * DIM)[hl];
            acc8(loA, hiA, va);
            acc8(loB, hiB, vb);
        }
        uint4* dst = reinterpret_cast<uint4*>(
            g_Mh + ((size_t)(tab * BATCH + b) * SLOTS + s0) * DIM);
        dst[hl]      = pack8(loA, hiA);
        dst[16 + hl] = pack8(loB, hiB);
    }
}

// ---------------------------------------------------------------------------
// K3: whole 3-hop chain, one block per batch element (unchanged).
// ---------------------------------------------------------------------------
__global__ void __launch_bounds__(HOP_T) hops_kernel(float* __restrict__ out)
{
    __shared__ float s_score[SLOTS];
    __shared__ float s_part[HW_HOP][DIM];
    __shared__ float s_u[DIM];
    __shared__ float s_red[16];

    const int b    = blockIdx.x;
    const int tid  = threadIdx.x;
    const int w    = tid >> 5;
    const int lane = tid & 31;
    const int hw   = tid >> 4;
    const int hl   = tid & 15;

    const __half* __restrict__ M1 = g_Mh + (size_t)(0 * BATCH + b) * SLOTS * DIM;
    const __half* __restrict__ M2 = g_Mh + (size_t)(1 * BATCH + b) * SLOTS * DIM;
    const __half* __restrict__ M3 = g_Mh + (size_t)(2 * BATCH + b) * SLOTS * DIM;

    // u1 = mean over slots of M1
    {
        float4 lo = make_float4(0.f, 0.f, 0.f, 0.f), hi = lo;
        #pragma unroll 5
        for (int k = 0; k < SL_HW; ++k) {
            uint4 v = reinterpret_cast<const uint4*>(
                M1 + (size_t)(hw * SL_HW + k) * DIM)[hl];
            acc8(lo, hi, v);
        }
        float* p = &s_part[hw][hl * 8];
        p[0] = lo.x; p[1] = lo.y; p[2] = lo.z; p[3] = lo.w;
        p[4] = hi.x; p[5] = hi.y; p[6] = hi.z; p[7] = hi.w;
    }
    __syncthreads();
    if (tid < DIM) {
        float s = 0.f;
        #pragma unroll
        for (int i = 0; i < HW_HOP; ++i) s += s_part[i][tid];
        s_u[tid] = s * (1.0f / SLOTS);
    }
    __syncthreads();

    #pragma unroll
    for (int hop = 0; hop < 2; ++hop) {
        const __half* Mk = (hop == 0) ? M1 : M2;
        const __half* Mv = (hop == 0) ? M2 : M3;

        float ur[8];
        #pragma unroll
        for (int j = 0; j < 8; ++j) ur[j] = s_u[hl * 8 + j];

        #pragma unroll 5
        for (int k = 0; k < SL_HW; ++k) {
            const int slot = hw * SL_HW + k;
            uint4 v = reinterpret_cast<const uint4*>(Mk + (size_t)slot * DIM)[hl];
            float p = hw_sum(dot8(v, ur));
            if (hl == 0) s_score[slot] = p;
        }
        __syncthreads();

        float mx = -1e30f;
        for (int i = tid; i < SLOTS; i += HOP_T) mx = fmaxf(mx, s_score[i]);
        mx = warp_max(mx);
        if (lane == 0) s_red[w] = mx;
        __syncthreads();
        mx = s_red[0];
        #pragma unroll
        for (int i = 1; i < 16; ++i) mx = fmaxf(mx, s_red[i]);

        float ss = 0.f;
        for (int i = tid; i < SLOTS; i += HOP_T) {
            float e = __expf(s_score[i] - mx);
            s_score[i] = e;
            ss += e;
        }
        ss = warp_sum(ss);
        __syncthreads();
        if (lane == 0) s_red[w] = ss;
        __syncthreads();
        ss = 0.f;
        #pragma unroll
        for (int i = 0; i < 16; ++i) ss += s_red[i];
        const float inv = 1.0f / ss;

        {
            float4 lo = make_float4(0.f, 0.f, 0.f, 0.f), hi = lo;
            #pragma unroll 5
            for (int k = 0; k < SL_HW; ++k) {
                const int slot = hw * SL_HW + k;
                const float p = s_score[slot];
                uint4 v = reinterpret_cast<const uint4*>(Mv + (size_t)slot * DIM)[hl];
                float2 f;
                f = __half22float2(*reinterpret_cast<__half2*>(&v.x)); lo.x += p * f.x; lo.y += p * f.y;
                f = __half22float2(*reinterpret_cast<__half2*>(&v.y)); lo.z += p * f.x; lo.w += p * f.y;
                f = __half22float2(*reinterpret_cast<__half2*>(&v.z)); hi.x += p * f.x; hi.y += p * f.y;
                f = __half22float2(*reinterpret_cast<__half2*>(&v.w)); hi.z += p * f.x; hi.w += p * f.y;
            }
            float* p = &s_part[hw][hl * 8];
            p[0] = lo.x; p[1] = lo.y; p[2] = lo.z; p[3] = lo.w;
            p[4] = hi.x; p[5] = hi.y; p[6] = hi.z; p[7] = hi.w;
        }
        __syncthreads();

        if (tid < DIM) {
            float o = 0.f;
            #pragma unroll
            for (int i = 0; i < HW_HOP; ++i) o += s_part[i][tid];
            const float un = s_u[tid] + o * inv;
            if (hop == 0) s_u[tid] = un;
            else          out[b * DIM + tid] = un;
        }
        __syncthreads();
    }
}

// ---------------------------------------------------------------------------
extern "C" void kernel_launch(void* const* d_in, const int* in_sizes, int n_in,
                              void* d_out, int out_size)
{
    const float* C     = (const float*)d_in[0];  // [4, 50257, 128]
    const int*   story = (const int*)  d_in[1];  // [32, 512, 6]
    const int*   kb    = (const int*)  d_in[2];  // [32, 128, 64]
    float*       out   = (float*)d_out;          // [32, 128]

    const int cb = (int)((CN / 8 + 255) / 256);              // 9424
    convert_kernel<<<cb, 256>>>(C);                          // fp32 -> fp16
    gather_kernel<<<3 * GBLK_TAB, 256>>>(story, kb);         // deep tree gather
    hops_kernel<<<BATCH, HOP_T>>>(out);                      // 3-hop chain
}